// round 2
// baseline (speedup 1.0000x reference)
#include <cuda_runtime.h>

#define N_TOTAL 100000
#define B_TOTAL 2048
#define F_DIM 16
#define D_DIM 64
#define NCH 32
#define NTILES ((N_TOTAL + 63) >> 6)   // 1563

// Scratch (allocation-free): precomputed scaled squared norms + deterministic partials
__device__ float g_xsqs[N_TOTAL];
__device__ float g_zsqs[B_TOTAL];
__device__ float g_part[NCH * B_TOTAL * F_DIM];

typedef unsigned long long u64;

__device__ __forceinline__ u64 fma2(u64 a, u64 b, u64 c) {
    u64 d;
    asm("fma.rn.f32x2 %0, %1, %2, %3;" : "=l"(d) : "l"(a), "l"(b), "l"(c));
    return d;
}
__device__ __forceinline__ u64 pack2(float lo, float hi) {
    u64 d;
    asm("mov.b64 %0, {%1, %2};" : "=l"(d) : "f"(lo), "f"(hi));
    return d;
}
__device__ __forceinline__ void unpack2(u64 v, float& lo, float& hi) {
    asm("mov.b64 {%0, %1}, %2;" : "=f"(lo), "=f"(hi) : "l"(v));
}

// Prologue: scaled squared norms. One warp per row (coalesced 64-float row read).
__global__ void rbf_pre(const float* __restrict__ z, const float* __restrict__ dataset) {
    int w = (blockIdx.x * blockDim.x + threadIdx.x) >> 5;
    int lane = threadIdx.x & 31;
    const float* src;
    float* dst;
    if (w < N_TOTAL) {
        src = dataset + (size_t)w * D_DIM;
        dst = g_xsqs + w;
    } else if (w < N_TOTAL + B_TOTAL) {
        src = z + (size_t)(w - N_TOTAL) * D_DIM;
        dst = g_zsqs + (w - N_TOTAL);
    } else {
        return;
    }
    float a = src[lane];
    float b = src[lane + 32];
    float s = a * a + b * b;
    #pragma unroll
    for (int o = 16; o; o >>= 1) s += __shfl_xor_sync(0xffffffffu, s, o);
    // pre-scale by 1/(2*ln2) so:  exp(-sq/2) = exp2f(cross*log2e - zs - xs)
    if (lane == 0) *dst = s * 0.72134752044448170f;
}

// Main fused kernel: 64(b) x 64(n) tile per block, 16x16 threads, 4x4 micro-tile.
// grid = (B/64, NCH); block (bx, cz) accumulates over n-tiles t = cz, cz+NCH, ...
__global__ void __launch_bounds__(256, 2)
rbf_main(const float* __restrict__ z, const float* __restrict__ dataset,
         const float* __restrict__ alpha) {
    // transposed (d-major) tiles; stride 66 keeps 8B alignment for float2 LDS
    // and gives only 2-way bank conflicts.
    __shared__ __align__(16) float zt[D_DIM][66];
    __shared__ __align__(16) float xt[D_DIM][66];
    __shared__ __align__(16) float at[64][18];   // alpha tile [n][f], pad->18
    __shared__ float zs_s[64];
    __shared__ float xs_s[64];

    const int tid = threadIdx.x;
    const int tx = tid & 15;
    const int ty = tid >> 4;
    const int b0 = blockIdx.x << 6;

    // Load z tile once (transposed). Global read coalesced along d.
    #pragma unroll
    for (int i = 0; i < 16; i++) {
        int e = tid + i * 256;
        int r = e >> 6, d = e & 63;
        zt[d][r] = z[(size_t)(b0 + r) * D_DIM + d];
    }
    if (tid < 64) zs_s[tid] = g_zsqs[b0 + tid];

    // Packed accumulators: 4 b-rows x 16 f (as 8 f32x2 pairs)
    u64 acc2[4][8];
    #pragma unroll
    for (int i = 0; i < 4; i++)
        #pragma unroll
        for (int p = 0; p < 8; p++) acc2[i][p] = 0ull;

    for (int t = blockIdx.y; t < NTILES; t += NCH) {
        const int n0 = t << 6;
        __syncthreads();   // protect previous tile's smem use

        // x tile (transposed) — pad rows beyond N with 0 (w forced to 0 via xs=1e30)
        #pragma unroll
        for (int i = 0; i < 16; i++) {
            int e = tid + i * 256;
            int r = e >> 6, d = e & 63;
            int n = n0 + r;
            xt[d][r] = (n < N_TOTAL) ? dataset[(size_t)n * D_DIM + d] : 0.f;
        }
        // alpha tile [n][f]
        #pragma unroll
        for (int i = 0; i < 4; i++) {
            int e = tid + i * 256;
            int r = e >> 4, f = e & 15;
            int n = n0 + r;
            at[r][f] = (n < N_TOTAL) ? alpha[(size_t)n * F_DIM + f] : 0.f;
        }
        if (tid < 64) {
            int n = n0 + tid;
            xs_s[tid] = (n < N_TOTAL) ? g_xsqs[n] : 1e30f;  // pad -> exp2f(-inf)=0
        }
        __syncthreads();

        // ---- cross = z . x^T  (packed f32x2 along the n dimension) ----
        u64 c2[4][2];
        #pragma unroll
        for (int i = 0; i < 4; i++) { c2[i][0] = 0ull; c2[i][1] = 0ull; }

        #pragma unroll 8
        for (int d = 0; d < D_DIM; d++) {
            u64 rx0 = *(const u64*)&xt[d][tx * 4];       // (x[n0j],x[n0j+1])
            u64 rx1 = *(const u64*)&xt[d][tx * 4 + 2];   // (x[n0j+2],x[n0j+3])
            #pragma unroll
            for (int i = 0; i < 4; i++) {
                float zv = zt[d][ty * 4 + i];
                u64 z2 = pack2(zv, zv);
                c2[i][0] = fma2(z2, rx0, c2[i][0]);
                c2[i][1] = fma2(z2, rx1, c2[i][1]);
            }
        }

        // ---- weights: w = exp2(cross*log2e - zs - xs) ----
        float zc[4], xc[4];
        #pragma unroll
        for (int i = 0; i < 4; i++) zc[i] = zs_s[ty * 4 + i];
        #pragma unroll
        for (int j = 0; j < 4; j++) xc[j] = xs_s[tx * 4 + j];

        float w[4][4];
        #pragma unroll
        for (int i = 0; i < 4; i++) {
            #pragma unroll
            for (int p = 0; p < 2; p++) {
                float clo, chi;
                unpack2(c2[i][p], clo, chi);
                w[i][2 * p]     = exp2f(fmaf(clo, 1.4426950408889634f, -(zc[i] + xc[2 * p])));
                w[i][2 * p + 1] = exp2f(fmaf(chi, 1.4426950408889634f, -(zc[i] + xc[2 * p + 1])));
            }
        }

        // ---- accumulate out += w * alpha (packed f32x2 along f) ----
        #pragma unroll
        for (int j = 0; j < 4; j++) {
            const int n = tx * 4 + j;
            u64 wp[4];
            #pragma unroll
            for (int i = 0; i < 4; i++) wp[i] = pack2(w[i][j], w[i][j]);
            #pragma unroll
            for (int p = 0; p < 8; p++) {
                u64 ap = *(const u64*)&at[n][2 * p];
                #pragma unroll
                for (int i = 0; i < 4; i++)
                    acc2[i][p] = fma2(wp[i], ap, acc2[i][p]);
            }
        }
    }

    // ---- reduce across the 16 tx lanes (within half-warp) ----
    // lane = (ty&1)*16 + tx, so xor masks {8,4,2,1} stay inside a tx group.
    float* part = g_part + (size_t)blockIdx.y * (B_TOTAL * F_DIM);
    #pragma unroll
    for (int i = 0; i < 4; i++) {
        #pragma unroll
        for (int p = 0; p < 8; p++) {
            float vlo, vhi;
            unpack2(acc2[i][p], vlo, vhi);
            #pragma unroll
            for (int o = 8; o; o >>= 1) {
                vlo += __shfl_xor_sync(0xffffffffu, vlo, o);
                vhi += __shfl_xor_sync(0xffffffffu, vhi, o);
            }
            if (tx == 0) {
                int b = b0 + ty * 4 + i;
                part[b * F_DIM + 2 * p]     = vlo;
                part[b * F_DIM + 2 * p + 1] = vhi;
            }
        }
    }
}

// Deterministic final reduction over the NCH partial buffers.
__global__ void rbf_reduce(float* __restrict__ out) {
    int gid = blockIdx.x * blockDim.x + threadIdx.x;
    if (gid >= B_TOTAL * F_DIM) return;
    float s = 0.f;
    #pragma unroll
    for (int c = 0; c < NCH; c++) s += g_part[c * (B_TOTAL * F_DIM) + gid];
    out[gid] = s;
}

extern "C" void kernel_launch(void* const* d_in, const int* in_sizes, int n_in,
                              void* d_out, int out_size) {
    const float* z       = (const float*)d_in[0];   // [2048, 64]
    const float* dataset = (const float*)d_in[1];   // [100000, 64]
    const float* alpha   = (const float*)d_in[2];   // [100000, 16]
    float* out = (float*)d_out;                     // [2048, 16]

    (void)in_sizes; (void)n_in; (void)out_size;

    const int rows = N_TOTAL + B_TOTAL;                 // one warp per row
    rbf_pre<<<(rows * 32 + 255) / 256, 256>>>(z, dataset);

    dim3 grid(B_TOTAL / 64, NCH);
    rbf_main<<<grid, 256>>>(z, dataset, alpha);

    rbf_reduce<<<(B_TOTAL * F_DIM + 255) / 256, 256>>>(out);
}

// round 4
// speedup vs baseline: 3.5832x; 3.5832x over previous
#include <cuda_runtime.h>
#include <cuda_bf16.h>
#include <cstdint>

#define B_TOTAL 2048
#define N_TOTAL 100000
#define F_DIM   16
#define TILE    128
#define NCHUNK  782           // ceil(100000/128)
#define NSPLIT  9
#define THREADS 256

#define L2E  1.4426950408889634f
#define L2EH 0.72134752044448170f

// ---- shared memory layout (byte offsets into dynamic smem) ----
#define SM_ZH   0            // z hi  bf16 [128][64] swizzled, 16KB
#define SM_ZL   16384        // z lo
#define SM_XH   32768        // x hi, 2 bufs x 16KB
#define SM_XL   65536        // x lo, 2 bufs x 16KB
#define SM_AH   98304        // alphaT hi [16][136] bf16 (4352B), 2 bufs
#define SM_AL   107008       // alphaT lo, 2 bufs
#define SM_XSN  115712       // x norms, 2 bufs x 128 f32
#define SM_ZSN  116736       // z norms, 128 f32
#define SMEM_BYTES 117248

__device__ float g_part[NSPLIT * B_TOTAL * F_DIM];

// ======================= helpers =======================
__device__ __forceinline__ uint32_t smem_u32(const void* p) {
    uint32_t a;
    asm("{ .reg .u64 t; cvta.to.shared.u64 t, %1; cvt.u32.u64 %0, t; }" : "=r"(a) : "l"(p));
    return a;
}
__device__ __forceinline__ void ldsm4(uint32_t r[4], uint32_t addr) {
    asm volatile("ldmatrix.sync.aligned.m8n8.x4.shared.b16 {%0,%1,%2,%3}, [%4];"
        : "=r"(r[0]), "=r"(r[1]), "=r"(r[2]), "=r"(r[3]) : "r"(addr));
}
__device__ __forceinline__ void mma_bf16(float c[4], const uint32_t a[4],
                                         uint32_t b0, uint32_t b1) {
    asm volatile("mma.sync.aligned.m16n8k16.row.col.f32.bf16.bf16.f32 "
        "{%0,%1,%2,%3}, {%4,%5,%6,%7}, {%8,%9}, {%0,%1,%2,%3};"
        : "+f"(c[0]), "+f"(c[1]), "+f"(c[2]), "+f"(c[3])
        : "r"(a[0]), "r"(a[1]), "r"(a[2]), "r"(a[3]), "r"(b0), "r"(b1));
}
// pack (lo, hi) floats -> bf16x2 (lo in low 16 bits)
__device__ __forceinline__ uint32_t pack_bf16(float hi, float lo) {
    __nv_bfloat162 t = __floats2bfloat162_rn(lo, hi);
    return *(uint32_t*)&t;
}
// swizzled byte offset inside a [128 rows][64 bf16] tile; c4 = float4 column (0..15)
__device__ __forceinline__ uint32_t sw_off(int row, int c4) {
    return (uint32_t)(row * 128 + (((c4 >> 1) ^ (row & 7)) << 4) + (c4 & 1) * 8);
}

// stage one x/alpha chunk into smem buffer `buf`
__device__ __forceinline__ void stage_x(char* sm, const float4* xv, const float* av,
                                        int buf, int cn, int tid) {
    const int r0 = tid >> 4, c4 = tid & 15;
    #pragma unroll
    for (int i = 0; i < 8; i++) {
        int row = r0 + 16 * i;
        float4 v = xv[i];
        uint32_t h01 = pack_bf16(v.y, v.x);
        uint32_t h23 = pack_bf16(v.w, v.z);
        float hx = __uint_as_float((h01 & 0xffffu) << 16);
        float hy = __uint_as_float(h01 & 0xffff0000u);
        float hz = __uint_as_float((h23 & 0xffffu) << 16);
        float hw = __uint_as_float(h23 & 0xffff0000u);
        uint32_t l01 = pack_bf16(v.y - hy, v.x - hx);
        uint32_t l23 = pack_bf16(v.w - hw, v.z - hz);
        uint32_t off = sw_off(row, c4);
        *(uint2*)(sm + SM_XH + buf * 16384 + off) = make_uint2(h01, h23);
        *(uint2*)(sm + SM_XL + buf * 16384 + off) = make_uint2(l01, l23);
        float s = v.x * v.x + v.y * v.y + v.z * v.z + v.w * v.w;
        s += __shfl_xor_sync(0xffffffffu, s, 1);
        s += __shfl_xor_sync(0xffffffffu, s, 2);
        s += __shfl_xor_sync(0xffffffffu, s, 4);
        s += __shfl_xor_sync(0xffffffffu, s, 8);
        if (c4 == 0) {
            int n = cn * TILE + row;
            *(float*)(sm + SM_XSN + buf * 512 + row * 4) =
                (n < N_TOTAL) ? s * L2EH : 1e30f;   // pad -> exp2(-huge)=0
        }
    }
    #pragma unroll
    for (int i = 0; i < 8; i++) {
        int idx = tid + 256 * i;
        int nl = idx >> 4, f = idx & 15;
        float a = av[i];
        __nv_bfloat16 bh = __float2bfloat16(a);
        float alo = a - __bfloat162float(bh);
        *(__nv_bfloat16*)(sm + SM_AH + buf * 4352 + f * 272 + nl * 2) = bh;
        *(__nv_bfloat16*)(sm + SM_AL + buf * 4352 + f * 272 + nl * 2) = __float2bfloat16(alo);
    }
}

// ======================= main fused kernel =======================
extern __shared__ char smem_dyn[];

__global__ void __launch_bounds__(THREADS, 1)
rbf_main(const float* __restrict__ z, const float* __restrict__ dataset,
         const float* __restrict__ alpha) {
    char* sm = smem_dyn;
    const uint32_t sb = smem_u32(sm);
    const int tid = threadIdx.x;
    const int l = tid & 31, w = tid >> 5;
    const int wm = w >> 1;          // 0..3, covers m32
    const int wn = w & 1;           // 0..1, covers n64
    const int m0 = blockIdx.x * TILE;
    const int split = blockIdx.y;
    const int r0 = tid >> 4, c4 = tid & 15;

    // ---- stage z tile (hi/lo bf16, swizzled) + z norms ----
    #pragma unroll
    for (int i = 0; i < 8; i++) {
        int row = r0 + 16 * i;
        float4 v = *(const float4*)(z + (size_t)(m0 + row) * 64 + c4 * 4);
        uint32_t h01 = pack_bf16(v.y, v.x);
        uint32_t h23 = pack_bf16(v.w, v.z);
        float hx = __uint_as_float((h01 & 0xffffu) << 16);
        float hy = __uint_as_float(h01 & 0xffff0000u);
        float hz = __uint_as_float((h23 & 0xffffu) << 16);
        float hw = __uint_as_float(h23 & 0xffff0000u);
        uint32_t l01 = pack_bf16(v.y - hy, v.x - hx);
        uint32_t l23 = pack_bf16(v.w - hw, v.z - hz);
        uint32_t off = sw_off(row, c4);
        *(uint2*)(sm + SM_ZH + off) = make_uint2(h01, h23);
        *(uint2*)(sm + SM_ZL + off) = make_uint2(l01, l23);
        float s = v.x * v.x + v.y * v.y + v.z * v.z + v.w * v.w;
        s += __shfl_xor_sync(0xffffffffu, s, 1);
        s += __shfl_xor_sync(0xffffffffu, s, 2);
        s += __shfl_xor_sync(0xffffffffu, s, 4);
        s += __shfl_xor_sync(0xffffffffu, s, 8);
        if (c4 == 0) *(float*)(sm + SM_ZSN + row * 4) = s * L2EH;
    }

    // ---- prefetch + stage chunk 0 ----
    float4 xv[8]; float av[8];
    {
        int cn = split;
        #pragma unroll
        for (int i = 0; i < 8; i++) {
            int n = cn * TILE + r0 + 16 * i;
            xv[i] = (n < N_TOTAL) ? *(const float4*)(dataset + (size_t)n * 64 + c4 * 4)
                                  : make_float4(0.f, 0.f, 0.f, 0.f);
        }
        #pragma unroll
        for (int i = 0; i < 8; i++) {
            int idx = tid + 256 * i;
            int n = cn * TILE + (idx >> 4);
            av[i] = (n < N_TOTAL) ? alpha[(size_t)n * F_DIM + (idx & 15)] : 0.f;
        }
        stage_x(sm, xv, av, 0, cn, tid);
    }
    __syncthreads();

    const int g = l >> 2;
    float zsv[2][2];
    #pragma unroll
    for (int mi = 0; mi < 2; mi++) {
        zsv[mi][0] = *(const float*)(sm + SM_ZSN + (wm * 32 + mi * 16 + g) * 4);
        zsv[mi][1] = *(const float*)(sm + SM_ZSN + (wm * 32 + mi * 16 + g + 8) * 4);
    }

    // ldmatrix lane geometry
    const int la_row = wm * 32 + (l & 15);               // A tile row (mi adds 16)
    const int la_k   = l >> 4;                           // A k half (0/1)
    const int lb_row = wn * 64 + ((l >> 4) << 3) + (l & 7);  // B tile row (ng adds 16)
    const int lb_k   = (l >> 3) & 1;                     // B k half
    const int r7     = l & 7;                            // row&7 (same for A and B)
    const uint32_t baseA_h = sb + SM_ZH + la_row * 128;
    const uint32_t baseA_l = sb + SM_ZL + la_row * 128;
    const uint32_t baseB   = (uint32_t)(lb_row * 128);
    const int lf_row = ((l >> 4) << 3) + (l & 7);        // alphaT f row
    const uint32_t baseAl  = (uint32_t)(lf_row * 272 + (wn * 64 + lb_k * 8) * 2);

    float o[2][2][4] = {};
    const int T = (NCHUNK - 1 - split) / NSPLIT + 1;
    int buf = 0;

    for (int t = 0; t < T; t++) {
        const bool more = (t + 1 < T);
        if (more) {
            int cn = split + (t + 1) * NSPLIT;
            #pragma unroll
            for (int i = 0; i < 8; i++) {
                int n = cn * TILE + r0 + 16 * i;
                xv[i] = (n < N_TOTAL) ? *(const float4*)(dataset + (size_t)n * 64 + c4 * 4)
                                      : make_float4(0.f, 0.f, 0.f, 0.f);
            }
            #pragma unroll
            for (int i = 0; i < 8; i++) {
                int idx = tid + 256 * i;
                int n = cn * TILE + (idx >> 4);
                av[i] = (n < N_TOTAL) ? alpha[(size_t)n * F_DIM + (idx & 15)] : 0.f;
            }
        }

        // ---- GEMM1: cross = z . x^T, bf16 3-pass split ----
        float cacc[2][8][4] = {};
        const uint32_t bufB_h = sb + SM_XH + buf * 16384 + baseB;
        const uint32_t bufB_l = sb + SM_XL + buf * 16384 + baseB;
        #pragma unroll
        for (int ks = 0; ks < 4; ks++) {
            uint32_t offA = (uint32_t)((((ks * 2 + la_k) ^ r7)) << 4);
            uint32_t offB = (uint32_t)((((ks * 2 + lb_k) ^ r7)) << 4);
            uint32_t ah[2][4], alo[2][4];
            ldsm4(ah[0],  baseA_h + offA);
            ldsm4(ah[1],  baseA_h + 2048 + offA);
            ldsm4(alo[0], baseA_l + offA);
            ldsm4(alo[1], baseA_l + 2048 + offA);
            #pragma unroll
            for (int ng = 0; ng < 4; ng++) {
                uint32_t bh[4], bl[4];
                ldsm4(bh, bufB_h + ng * 2048 + offB);
                ldsm4(bl, bufB_l + ng * 2048 + offB);
                #pragma unroll
                for (int mi = 0; mi < 2; mi++) {
                    mma_bf16(cacc[mi][2 * ng],     ah[mi],  bh[0], bh[1]);
                    mma_bf16(cacc[mi][2 * ng + 1], ah[mi],  bh[2], bh[3]);
                    mma_bf16(cacc[mi][2 * ng],     alo[mi], bh[0], bh[1]);
                    mma_bf16(cacc[mi][2 * ng + 1], alo[mi], bh[2], bh[3]);
                    mma_bf16(cacc[mi][2 * ng],     ah[mi],  bl[0], bl[1]);
                    mma_bf16(cacc[mi][2 * ng + 1], ah[mi],  bl[2], bl[3]);
                }
            }
        }

        // ---- epilogue + GEMM2, interleaved per k16 group of n ----
        const uint32_t aTb_h = sb + SM_AH + buf * 4352 + baseAl;
        const uint32_t aTb_l = sb + SM_AL + buf * 4352 + baseAl;
        #pragma unroll
        for (int ks2 = 0; ks2 < 4; ks2++) {
            uint32_t fh[2][4], fl[2][4];
            #pragma unroll
            for (int mi = 0; mi < 2; mi++) {
                #pragma unroll
                for (int q = 0; q < 2; q++) {
                    int nt = 2 * ks2 + q;
                    float2 xsp = *(const float2*)(sm + SM_XSN + buf * 512 +
                                                  (wn * 64 + nt * 8 + (l & 3) * 2) * 4);
                    float* c = cacc[mi][nt];
                    float w0 = exp2f(fmaf(c[0], L2E, -(zsv[mi][0] + xsp.x)));
                    float w1 = exp2f(fmaf(c[1], L2E, -(zsv[mi][0] + xsp.y)));
                    float w2 = exp2f(fmaf(c[2], L2E, -(zsv[mi][1] + xsp.x)));
                    float w3 = exp2f(fmaf(c[3], L2E, -(zsv[mi][1] + xsp.y)));
                    uint32_t p01 = pack_bf16(w1, w0);
                    uint32_t p23 = pack_bf16(w3, w2);
                    float h0 = __uint_as_float((p01 & 0xffffu) << 16);
                    float h1 = __uint_as_float(p01 & 0xffff0000u);
                    float h2 = __uint_as_float((p23 & 0xffffu) << 16);
                    float h3 = __uint_as_float(p23 & 0xffff0000u);
                    fh[mi][2 * q]     = p01;
                    fh[mi][2 * q + 1] = p23;
                    fl[mi][2 * q]     = pack_bf16(w1 - h1, w0 - h0);
                    fl[mi][2 * q + 1] = pack_bf16(w3 - h3, w2 - h2);
                }
            }
            uint32_t bh2[4], bl2[4];
            ldsm4(bh2, aTb_h + ks2 * 32);
            ldsm4(bl2, aTb_l + ks2 * 32);
            #pragma unroll
            for (int mi = 0; mi < 2; mi++) {
                mma_bf16(o[mi][0], fh[mi], bh2[0], bh2[1]);
                mma_bf16(o[mi][1], fh[mi], bh2[2], bh2[3]);
                mma_bf16(o[mi][0], fl[mi], bh2[0], bh2[1]);
                mma_bf16(o[mi][1], fl[mi], bh2[2], bh2[3]);
                mma_bf16(o[mi][0], fh[mi], bl2[0], bl2[1]);
                mma_bf16(o[mi][1], fh[mi], bl2[2], bl2[3]);
            }
        }

        __syncthreads();
        if (more) {
            stage_x(sm, xv, av, buf ^ 1, split + (t + 1) * NSPLIT, tid);
            __syncthreads();
            buf ^= 1;
        }
    }

    // ---- reduce across the 2 wn warps, write partials ----
    __syncthreads();
    float* red = (float*)sm;                 // [128][16] f32, reuses z-tile space
    if (wn == 1) {
        #pragma unroll
        for (int mi = 0; mi < 2; mi++)
            #pragma unroll
            for (int ft = 0; ft < 2; ft++) {
                int mr = wm * 32 + mi * 16 + g;
                int f0 = ft * 8 + (l & 3) * 2;
                red[mr * 16 + f0]           = o[mi][ft][0];
                red[mr * 16 + f0 + 1]       = o[mi][ft][1];
                red[(mr + 8) * 16 + f0]     = o[mi][ft][2];
                red[(mr + 8) * 16 + f0 + 1] = o[mi][ft][3];
            }
    }
    __syncthreads();
    if (wn == 0) {
        float* dst = g_part + ((size_t)split * B_TOTAL + m0) * F_DIM;
        #pragma unroll
        for (int mi = 0; mi < 2; mi++)
            #pragma unroll
            for (int ft = 0; ft < 2; ft++) {
                int mr = wm * 32 + mi * 16 + g;
                int f0 = ft * 8 + (l & 3) * 2;
                dst[mr * 16 + f0]           = o[mi][ft][0] + red[mr * 16 + f0];
                dst[mr * 16 + f0 + 1]       = o[mi][ft][1] + red[mr * 16 + f0 + 1];
                dst[(mr + 8) * 16 + f0]     = o[mi][ft][2] + red[(mr + 8) * 16 + f0];
                dst[(mr + 8) * 16 + f0 + 1] = o[mi][ft][3] + red[(mr + 8) * 16 + f0 + 1];
            }
    }
}

// Deterministic reduction of the NSPLIT partial buffers.
__global__ void rbf_reduce(float* __restrict__ out) {
    int gid = blockIdx.x * blockDim.x + threadIdx.x;
    if (gid >= B_TOTAL * F_DIM) return;
    float s = 0.f;
    #pragma unroll
    for (int c = 0; c < NSPLIT; c++) s += g_part[(size_t)c * (B_TOTAL * F_DIM) + gid];
    out[gid] = s;
}

extern "C" void kernel_launch(void* const* d_in, const int* in_sizes, int n_in,
                              void* d_out, int out_size) {
    const float* z       = (const float*)d_in[0];   // [2048, 64]
    const float* dataset = (const float*)d_in[1];   // [100000, 64]
    const float* alpha   = (const float*)d_in[2];   // [100000, 16]
    float* out = (float*)d_out;                     // [2048, 16]
    (void)in_sizes; (void)n_in; (void)out_size;

    cudaFuncSetAttribute(rbf_main, cudaFuncAttributeMaxDynamicSharedMemorySize, SMEM_BYTES);
    dim3 grid(B_TOTAL / TILE, NSPLIT);
    rbf_main<<<grid, THREADS, SMEM_BYTES>>>(z, dataset, alpha);
    rbf_reduce<<<(B_TOTAL * F_DIM + 255) / 256, 256>>>(out);
}

// round 5
// speedup vs baseline: 3.7279x; 1.0404x over previous
#include <cuda_runtime.h>
#include <cuda_bf16.h>
#include <cstdint>

#define B_TOTAL 2048
#define N_TOTAL 100000
#define F_DIM   16
#define TILE    128
#define NCHUNK  782           // ceil(100000/128)
#define NSPLIT  9
#define THREADS 512

#define L2E  1.4426950408889634f
#define L2EH 0.72134752044448170f

// ---- shared memory layout (byte offsets into dynamic smem) ----
#define SM_ZH   0            // z hi  bf16 [128][64] swizzled, 16KB
#define SM_ZL   16384        // z lo
#define SM_XH   32768        // x hi, 2 bufs x 16KB
#define SM_XL   65536        // x lo, 2 bufs x 16KB
#define SM_AH   98304        // alphaT hi [16][136] bf16 (4352B), 2 bufs
#define SM_AL   107008       // alphaT lo, 2 bufs
#define SM_XSN  115712       // x norms, 2 bufs x 128 f32
#define SM_ZSN  116736       // z norms, 128 f32
#define SMEM_BYTES 117248

__device__ float g_part[NSPLIT * B_TOTAL * F_DIM];

// ======================= helpers =======================
__device__ __forceinline__ uint32_t smem_u32(const void* p) {
    uint32_t a;
    asm("{ .reg .u64 t; cvta.to.shared.u64 t, %1; cvt.u32.u64 %0, t; }" : "=r"(a) : "l"(p));
    return a;
}
__device__ __forceinline__ void ldsm4(uint32_t r[4], uint32_t addr) {
    asm volatile("ldmatrix.sync.aligned.m8n8.x4.shared.b16 {%0,%1,%2,%3}, [%4];"
        : "=r"(r[0]), "=r"(r[1]), "=r"(r[2]), "=r"(r[3]) : "r"(addr));
}
__device__ __forceinline__ void mma_bf16(float c[4], const uint32_t a[4],
                                         uint32_t b0, uint32_t b1) {
    asm volatile("mma.sync.aligned.m16n8k16.row.col.f32.bf16.bf16.f32 "
        "{%0,%1,%2,%3}, {%4,%5,%6,%7}, {%8,%9}, {%0,%1,%2,%3};"
        : "+f"(c[0]), "+f"(c[1]), "+f"(c[2]), "+f"(c[3])
        : "r"(a[0]), "r"(a[1]), "r"(a[2]), "r"(a[3]), "r"(b0), "r"(b1));
}
__device__ __forceinline__ float ex2f(float x) {
    float r; asm("ex2.approx.ftz.f32 %0, %1;" : "=f"(r) : "f"(x)); return r;
}
// pack (lo, hi) floats -> bf16x2 (lo in low 16 bits)
__device__ __forceinline__ uint32_t pack_bf16(float hi, float lo) {
    __nv_bfloat162 t = __floats2bfloat162_rn(lo, hi);
    return *(uint32_t*)&t;
}
// swizzled byte offset inside a [128 rows][64 bf16] tile; c4 = float4 column (0..15)
__device__ __forceinline__ uint32_t sw_off(int row, int c4) {
    return (uint32_t)(row * 128 + (((c4 >> 1) ^ (row & 7)) << 4) + (c4 & 1) * 8);
}

// stage one x/alpha chunk into smem buffer `buf` (512-thread version)
__device__ __forceinline__ void stage_x(char* sm, const float4* xv, const float* av,
                                        int buf, int cn, int tid) {
    const int r0 = tid >> 4, c4 = tid & 15;
    #pragma unroll
    for (int i = 0; i < 4; i++) {
        int row = r0 + 32 * i;
        float4 v = xv[i];
        uint32_t h01 = pack_bf16(v.y, v.x);
        uint32_t h23 = pack_bf16(v.w, v.z);
        float hx = __uint_as_float((h01 & 0xffffu) << 16);
        float hy = __uint_as_float(h01 & 0xffff0000u);
        float hz = __uint_as_float((h23 & 0xffffu) << 16);
        float hw = __uint_as_float(h23 & 0xffff0000u);
        uint32_t l01 = pack_bf16(v.y - hy, v.x - hx);
        uint32_t l23 = pack_bf16(v.w - hw, v.z - hz);
        uint32_t off = sw_off(row, c4);
        *(uint2*)(sm + SM_XH + buf * 16384 + off) = make_uint2(h01, h23);
        *(uint2*)(sm + SM_XL + buf * 16384 + off) = make_uint2(l01, l23);
        float s = v.x * v.x + v.y * v.y + v.z * v.z + v.w * v.w;
        s += __shfl_xor_sync(0xffffffffu, s, 1);
        s += __shfl_xor_sync(0xffffffffu, s, 2);
        s += __shfl_xor_sync(0xffffffffu, s, 4);
        s += __shfl_xor_sync(0xffffffffu, s, 8);
        if (c4 == 0) {
            int n = cn * TILE + row;
            *(float*)(sm + SM_XSN + buf * 512 + row * 4) =
                (n < N_TOTAL) ? s * L2EH : 1e30f;   // pad -> exp2(-huge)=0
        }
    }
    #pragma unroll
    for (int i = 0; i < 4; i++) {
        int idx = tid + THREADS * i;
        int nl = idx >> 4, f = idx & 15;
        float a = av[i];
        __nv_bfloat16 bh = __float2bfloat16(a);
        float alo = a - __bfloat162float(bh);
        *(__nv_bfloat16*)(sm + SM_AH + buf * 4352 + f * 272 + nl * 2) = bh;
        *(__nv_bfloat16*)(sm + SM_AL + buf * 4352 + f * 272 + nl * 2) = __float2bfloat16(alo);
    }
}

// ======================= main fused kernel =======================
extern __shared__ char smem_dyn[];

__global__ void __launch_bounds__(THREADS, 1)
rbf_main(const float* __restrict__ z, const float* __restrict__ dataset,
         const float* __restrict__ alpha) {
    char* sm = smem_dyn;
    const uint32_t sb = smem_u32(sm);
    const int tid = threadIdx.x;
    const int l = tid & 31, w = tid >> 5;
    const int wm = w >> 2;          // 0..3 -> m32
    const int wn = w & 3;           // 0..3 -> n32
    const int m0 = blockIdx.x * TILE;
    const int split = blockIdx.y;
    const int r0 = tid >> 4, c4 = tid & 15;

    // ---- stage z tile (hi/lo bf16, swizzled) + z norms ----
    #pragma unroll
    for (int i = 0; i < 4; i++) {
        int row = r0 + 32 * i;
        float4 v = *(const float4*)(z + (size_t)(m0 + row) * 64 + c4 * 4);
        uint32_t h01 = pack_bf16(v.y, v.x);
        uint32_t h23 = pack_bf16(v.w, v.z);
        float hx = __uint_as_float((h01 & 0xffffu) << 16);
        float hy = __uint_as_float(h01 & 0xffff0000u);
        float hz = __uint_as_float((h23 & 0xffffu) << 16);
        float hw = __uint_as_float(h23 & 0xffff0000u);
        uint32_t l01 = pack_bf16(v.y - hy, v.x - hx);
        uint32_t l23 = pack_bf16(v.w - hw, v.z - hz);
        uint32_t off = sw_off(row, c4);
        *(uint2*)(sm + SM_ZH + off) = make_uint2(h01, h23);
        *(uint2*)(sm + SM_ZL + off) = make_uint2(l01, l23);
        float s = v.x * v.x + v.y * v.y + v.z * v.z + v.w * v.w;
        s += __shfl_xor_sync(0xffffffffu, s, 1);
        s += __shfl_xor_sync(0xffffffffu, s, 2);
        s += __shfl_xor_sync(0xffffffffu, s, 4);
        s += __shfl_xor_sync(0xffffffffu, s, 8);
        if (c4 == 0) *(float*)(sm + SM_ZSN + row * 4) = s * L2EH;
    }

    // ---- prefetch + stage chunk 0 ----
    float4 xv[4]; float av[4];
    {
        int cn = split;
        #pragma unroll
        for (int i = 0; i < 4; i++) {
            int n = cn * TILE + r0 + 32 * i;
            xv[i] = (n < N_TOTAL) ? *(const float4*)(dataset + (size_t)n * 64 + c4 * 4)
                                  : make_float4(0.f, 0.f, 0.f, 0.f);
        }
        #pragma unroll
        for (int i = 0; i < 4; i++) {
            int idx = tid + THREADS * i;
            int n = cn * TILE + (idx >> 4);
            av[i] = (n < N_TOTAL) ? alpha[(size_t)n * F_DIM + (idx & 15)] : 0.f;
        }
        stage_x(sm, xv, av, 0, cn, tid);
    }
    __syncthreads();

    const int g = l >> 2;
    float zsv[2][2];
    #pragma unroll
    for (int mi = 0; mi < 2; mi++) {
        zsv[mi][0] = *(const float*)(sm + SM_ZSN + (wm * 32 + mi * 16 + g) * 4);
        zsv[mi][1] = *(const float*)(sm + SM_ZSN + (wm * 32 + mi * 16 + g + 8) * 4);
    }

    // ldmatrix lane geometry
    const int la_row = wm * 32 + (l & 15);
    const int la_k   = l >> 4;
    const int lb_row = wn * 32 + ((l >> 4) << 3) + (l & 7);
    const int lb_k   = (l >> 3) & 1;
    const int r7     = l & 7;
    const uint32_t baseA_h = sb + SM_ZH + la_row * 128;
    const uint32_t baseA_l = sb + SM_ZL + la_row * 128;
    const uint32_t baseB   = (uint32_t)(lb_row * 128);
    const int lf_row = ((l >> 4) << 3) + (l & 7);
    const uint32_t baseAl  = (uint32_t)(lf_row * 272 + (wn * 32 + ((l >> 3) & 1) * 8) * 2);

    float o[2][2][4] = {};
    const int T = (NCHUNK - 1 - split) / NSPLIT + 1;
    int buf = 0;

    for (int t = 0; t < T; t++) {
        const bool more = (t + 1 < T);
        // ---- prefetch chunk t+1 (independent; LDGs issue early) ----
        if (more) {
            int cn = split + (t + 1) * NSPLIT;
            #pragma unroll
            for (int i = 0; i < 4; i++) {
                int n = cn * TILE + r0 + 32 * i;
                xv[i] = (n < N_TOTAL) ? *(const float4*)(dataset + (size_t)n * 64 + c4 * 4)
                                      : make_float4(0.f, 0.f, 0.f, 0.f);
            }
            #pragma unroll
            for (int i = 0; i < 4; i++) {
                int idx = tid + THREADS * i;
                int n = cn * TILE + (idx >> 4);
                av[i] = (n < N_TOTAL) ? alpha[(size_t)n * F_DIM + (idx & 15)] : 0.f;
            }
        }

        // ---- GEMM1: cross = z . x^T, bf16 3-pass split ----
        float cacc[2][4][4] = {};
        const uint32_t bufB_h = sb + SM_XH + buf * 16384 + baseB;
        const uint32_t bufB_l = sb + SM_XL + buf * 16384 + baseB;
        #pragma unroll
        for (int ks = 0; ks < 4; ks++) {
            uint32_t offA = (uint32_t)(((ks * 2 + la_k) ^ r7) << 4);
            uint32_t offB = (uint32_t)(((ks * 2 + lb_k) ^ r7) << 4);
            uint32_t ah[2][4], alo[2][4];
            ldsm4(ah[0],  baseA_h + offA);
            ldsm4(ah[1],  baseA_h + 2048 + offA);
            ldsm4(alo[0], baseA_l + offA);
            ldsm4(alo[1], baseA_l + 2048 + offA);
            #pragma unroll
            for (int ng = 0; ng < 2; ng++) {
                uint32_t bh[4], bl[4];
                ldsm4(bh, bufB_h + ng * 2048 + offB);
                ldsm4(bl, bufB_l + ng * 2048 + offB);
                #pragma unroll
                for (int mi = 0; mi < 2; mi++) {
                    mma_bf16(cacc[mi][2 * ng],     ah[mi],  bh[0], bh[1]);
                    mma_bf16(cacc[mi][2 * ng + 1], ah[mi],  bh[2], bh[3]);
                    mma_bf16(cacc[mi][2 * ng],     alo[mi], bh[0], bh[1]);
                    mma_bf16(cacc[mi][2 * ng + 1], alo[mi], bh[2], bh[3]);
                    mma_bf16(cacc[mi][2 * ng],     ah[mi],  bl[0], bl[1]);
                    mma_bf16(cacc[mi][2 * ng + 1], ah[mi],  bl[2], bl[3]);
                }
            }
        }

        // ---- stage chunk t+1 while GEMM1 HMMAs drain ----
        if (more) stage_x(sm, xv, av, buf ^ 1, split + (t + 1) * NSPLIT, tid);

        // ---- epilogue + GEMM2 ----
        const uint32_t aTb_h = sb + SM_AH + buf * 4352 + baseAl;
        const uint32_t aTb_l = sb + SM_AL + buf * 4352 + baseAl;
        #pragma unroll
        for (int ks2 = 0; ks2 < 2; ks2++) {
            uint32_t fh[2][4], fl[2][4];
            #pragma unroll
            for (int mi = 0; mi < 2; mi++) {
                #pragma unroll
                for (int q = 0; q < 2; q++) {
                    int nt = 2 * ks2 + q;
                    float2 xsp = *(const float2*)(sm + SM_XSN + buf * 512 +
                                                  (wn * 32 + nt * 8 + (l & 3) * 2) * 4);
                    float* c = cacc[mi][nt];
                    float w0 = ex2f(fmaf(c[0], L2E, -(zsv[mi][0] + xsp.x)));
                    float w1 = ex2f(fmaf(c[1], L2E, -(zsv[mi][0] + xsp.y)));
                    float w2 = ex2f(fmaf(c[2], L2E, -(zsv[mi][1] + xsp.x)));
                    float w3 = ex2f(fmaf(c[3], L2E, -(zsv[mi][1] + xsp.y)));
                    uint32_t p01 = pack_bf16(w1, w0);
                    uint32_t p23 = pack_bf16(w3, w2);
                    float h0 = __uint_as_float((p01 & 0xffffu) << 16);
                    float h1 = __uint_as_float(p01 & 0xffff0000u);
                    float h2 = __uint_as_float((p23 & 0xffffu) << 16);
                    float h3 = __uint_as_float(p23 & 0xffff0000u);
                    fh[mi][2 * q]     = p01;
                    fh[mi][2 * q + 1] = p23;
                    fl[mi][2 * q]     = pack_bf16(w1 - h1, w0 - h0);
                    fl[mi][2 * q + 1] = pack_bf16(w3 - h3, w2 - h2);
                }
            }
            uint32_t bh2[4], bl2[4];
            ldsm4(bh2, aTb_h + ks2 * 32);
            ldsm4(bl2, aTb_l + ks2 * 32);
            #pragma unroll
            for (int mi = 0; mi < 2; mi++) {
                mma_bf16(o[mi][0], fh[mi], bh2[0], bh2[1]);
                mma_bf16(o[mi][1], fh[mi], bh2[2], bh2[3]);
                mma_bf16(o[mi][0], fl[mi], bh2[0], bh2[1]);
                mma_bf16(o[mi][1], fl[mi], bh2[2], bh2[3]);
                mma_bf16(o[mi][0], fh[mi], bl2[0], bl2[1]);
                mma_bf16(o[mi][1], fh[mi], bl2[2], bl2[3]);
            }
        }

        __syncthreads();
        if (more) buf ^= 1;
    }

    // ---- reduce across the 4 wn warps, write partials ----
    float* red = (float*)sm;                 // 3 x [128][16] f32, reuses z-tile space
    if (wn != 0) {
        float* dst = red + (size_t)(wn - 1) * 2048;
        #pragma unroll
        for (int mi = 0; mi < 2; mi++)
            #pragma unroll
            for (int ft = 0; ft < 2; ft++) {
                int mr = wm * 32 + mi * 16 + g;
                int f0 = ft * 8 + (l & 3) * 2;
                *(float2*)(dst + mr * 16 + f0)       = make_float2(o[mi][ft][0], o[mi][ft][1]);
                *(float2*)(dst + (mr + 8) * 16 + f0) = make_float2(o[mi][ft][2], o[mi][ft][3]);
            }
    }
    __syncthreads();
    if (wn == 0) {
        float* dst = g_part + ((size_t)split * B_TOTAL + m0) * F_DIM;
        #pragma unroll
        for (int mi = 0; mi < 2; mi++)
            #pragma unroll
            for (int ft = 0; ft < 2; ft++) {
                int mr = wm * 32 + mi * 16 + g;
                int f0 = ft * 8 + (l & 3) * 2;
                float s0 = o[mi][ft][0], s1 = o[mi][ft][1];
                float s2 = o[mi][ft][2], s3 = o[mi][ft][3];
                #pragma unroll
                for (int c = 0; c < 3; c++) {
                    float2 a = *(float2*)(red + (size_t)c * 2048 + mr * 16 + f0);
                    float2 b = *(float2*)(red + (size_t)c * 2048 + (mr + 8) * 16 + f0);
                    s0 += a.x; s1 += a.y; s2 += b.x; s3 += b.y;
                }
                *(float2*)(dst + mr * 16 + f0)       = make_float2(s0, s1);
                *(float2*)(dst + (mr + 8) * 16 + f0) = make_float2(s2, s3);
            }
    }
}

// Deterministic reduction of the NSPLIT partial buffers.
__global__ void rbf_reduce(float* __restrict__ out) {
    int gid = blockIdx.x * blockDim.x + threadIdx.x;
    if (gid >= B_TOTAL * F_DIM) return;
    float s = 0.f;
    #pragma unroll
    for (int c = 0; c < NSPLIT; c++) s += g_part[(size_t)c * (B_TOTAL * F_DIM) + gid];
    out[gid] = s;
}

extern "C" void kernel_launch(void* const* d_in, const int* in_sizes, int n_in,
                              void* d_out, int out_size) {
    const float* z       = (const float*)d_in[0];   // [2048, 64]
    const float* dataset = (const float*)d_in[1];   // [100000, 64]
    const float* alpha   = (const float*)d_in[2];   // [100000, 16]
    float* out = (float*)d_out;                     // [2048, 16]
    (void)in_sizes; (void)n_in; (void)out_size;

    cudaFuncSetAttribute(rbf_main, cudaFuncAttributeMaxDynamicSharedMemorySize, SMEM_BYTES);
    dim3 grid(B_TOTAL / TILE, NSPLIT);
    rbf_main<<<grid, THREADS, SMEM_BYTES>>>(z, dataset, alpha);
    rbf_reduce<<<(B_TOTAL * F_DIM + 255) / 256, 256>>>(out);
}

// round 7
// speedup vs baseline: 3.8885x; 1.0431x over previous
#include <cuda_runtime.h>
#include <cuda_bf16.h>
#include <cstdint>

#define B_TOTAL 2048
#define N_TOTAL 100000
#define N_PAD   100096
#define F_DIM   16
#define TILE_M  256
#define CHUNK   128
#define NCHUNK  782           // ceil(100000/128)
#define NSPLIT  18
#define THREADS 512

#define L2E  1.4426950408889634f
#define L2EH 0.72134752044448170f

// ---- preconverted operand storage (device globals; allocation-free) ----
__device__ __nv_bfloat16 g_xh[(size_t)N_PAD * 64];
__device__ __nv_bfloat16 g_xl[(size_t)N_PAD * 64];
__device__ __nv_bfloat16 g_zh[B_TOTAL * 64];
__device__ __nv_bfloat16 g_zl[B_TOTAL * 64];
__device__ __nv_bfloat16 g_ath[(size_t)16 * N_PAD];  // alphaT hi [f][n] bf16
__device__ __nv_bfloat16 g_atl[(size_t)16 * N_PAD];  // alphaT lo
__device__ float         g_xs[N_PAD];                // ||x||^2 * L2EH (pad -> 1e30)
__device__ float         g_zs[B_TOTAL];              // ||z||^2 * L2EH
__device__ float         g_part[NSPLIT * B_TOTAL * F_DIM];

// ---- shared memory layout (byte offsets) ----
#define SM_ZH   0            // z hi bf16 [256][64] swizzled, 32KB
#define SM_ZL   32768
#define SM_XH   65536        // x hi, 2 bufs x 16KB
#define SM_XL   98304
#define SM_ATH  131072       // alphaT hi bf16 [16][136], 2 bufs x 4352B
#define SM_ATL  139776       // alphaT lo, 2 bufs x 4352B
#define SM_XSN  148480       // x norms, 2 bufs x 512B
#define SM_ZSN  149504       // z norms, 256 f32
#define SMEM_BYTES 150528

// ======================= helpers =======================
__device__ __forceinline__ uint32_t smem_u32(const void* p) {
    uint32_t a;
    asm("{ .reg .u64 t; cvta.to.shared.u64 t, %1; cvt.u32.u64 %0, t; }" : "=r"(a) : "l"(p));
    return a;
}
__device__ __forceinline__ void ldsm4(uint32_t r[4], uint32_t addr) {
    asm volatile("ldmatrix.sync.aligned.m8n8.x4.shared.b16 {%0,%1,%2,%3}, [%4];"
        : "=r"(r[0]), "=r"(r[1]), "=r"(r[2]), "=r"(r[3]) : "r"(addr));
}
__device__ __forceinline__ void mma_bf16(float c[4], const uint32_t a[4],
                                         uint32_t b0, uint32_t b1) {
    asm volatile("mma.sync.aligned.m16n8k16.row.col.f32.bf16.bf16.f32 "
        "{%0,%1,%2,%3}, {%4,%5,%6,%7}, {%8,%9}, {%0,%1,%2,%3};"
        : "+f"(c[0]), "+f"(c[1]), "+f"(c[2]), "+f"(c[3])
        : "r"(a[0]), "r"(a[1]), "r"(a[2]), "r"(a[3]), "r"(b0), "r"(b1));
}
__device__ __forceinline__ float ex2f(float x) {
    float r; asm("ex2.approx.ftz.f32 %0, %1;" : "=f"(r) : "f"(x)); return r;
}
// pack (hi_val, lo_val) -> bf16x2 with lo_val in low 16 bits
__device__ __forceinline__ uint32_t pack_bf16(float hi, float lo) {
    __nv_bfloat162 t = __floats2bfloat162_rn(lo, hi);
    return *(uint32_t*)&t;
}
__device__ __forceinline__ void cpa16(uint32_t dst, const void* src) {
    asm volatile("cp.async.cg.shared.global [%0], [%1], 16;" :: "r"(dst), "l"(src));
}
__device__ __forceinline__ void cpa4(uint32_t dst, const void* src) {
    asm volatile("cp.async.ca.shared.global [%0], [%1], 4;" :: "r"(dst), "l"(src));
}
#define CP_COMMIT() asm volatile("cp.async.commit_group;" ::: "memory")
#define CP_WAIT0()  asm volatile("cp.async.wait_group 0;" ::: "memory")

// swizzled 16B-granule offset in a [rows][64 bf16] tile; c = 16B column (0..7)
__device__ __forceinline__ uint32_t swz(int row, int c) {
    return (uint32_t)(row * 128 + ((c ^ (row & 7)) << 4));
}

// ======================= prep kernels =======================
// One warp per row: bf16 hi/lo split + scaled norm for dataset and z.
__global__ void prep_rows(const float* __restrict__ z, const float* __restrict__ dataset) {
    int r = (blockIdx.x * blockDim.x + threadIdx.x) >> 5;
    int lane = threadIdx.x & 31;
    if (r < N_PAD) {
        float a = 0.f, b = 0.f;
        if (r < N_TOTAL) {
            a = dataset[(size_t)r * 64 + lane];
            b = dataset[(size_t)r * 64 + lane + 32];
        }
        float s = a * a + b * b;
        #pragma unroll
        for (int o = 16; o; o >>= 1) s += __shfl_xor_sync(0xffffffffu, s, o);
        __nv_bfloat16 ah = __float2bfloat16(a), bh = __float2bfloat16(b);
        g_xh[(size_t)r * 64 + lane]      = ah;
        g_xh[(size_t)r * 64 + lane + 32] = bh;
        g_xl[(size_t)r * 64 + lane]      = __float2bfloat16(a - __bfloat162float(ah));
        g_xl[(size_t)r * 64 + lane + 32] = __float2bfloat16(b - __bfloat162float(bh));
        if (lane == 0) g_xs[r] = (r < N_TOTAL) ? s * L2EH : 1e30f;
    } else if (r < N_PAD + B_TOTAL) {
        int q = r - N_PAD;
        float a = z[(size_t)q * 64 + lane];
        float b = z[(size_t)q * 64 + lane + 32];
        float s = a * a + b * b;
        #pragma unroll
        for (int o = 16; o; o >>= 1) s += __shfl_xor_sync(0xffffffffu, s, o);
        __nv_bfloat16 ah = __float2bfloat16(a), bh = __float2bfloat16(b);
        g_zh[(size_t)q * 64 + lane]      = ah;
        g_zh[(size_t)q * 64 + lane + 32] = bh;
        g_zl[(size_t)q * 64 + lane]      = __float2bfloat16(a - __bfloat162float(ah));
        g_zl[(size_t)q * 64 + lane + 32] = __float2bfloat16(b - __bfloat162float(bh));
        if (lane == 0) g_zs[q] = s * L2EH;
    }
}

// One thread per n: transpose alpha [n][16] -> g_ath/g_atl [16][N_PAD] bf16 hi/lo.
__global__ void prep_at(const float* __restrict__ alpha) {
    int n = blockIdx.x * blockDim.x + threadIdx.x;
    if (n >= N_PAD) return;
    float v[16];
    if (n < N_TOTAL) {
        #pragma unroll
        for (int f = 0; f < 4; f++) {
            float4 t = *(const float4*)(alpha + (size_t)n * 16 + f * 4);
            v[4*f] = t.x; v[4*f+1] = t.y; v[4*f+2] = t.z; v[4*f+3] = t.w;
        }
    } else {
        #pragma unroll
        for (int f = 0; f < 16; f++) v[f] = 0.f;
    }
    #pragma unroll
    for (int f = 0; f < 16; f++) {
        __nv_bfloat16 h = __float2bfloat16(v[f]);
        g_ath[(size_t)f * N_PAD + n] = h;
        g_atl[(size_t)f * N_PAD + n] = __float2bfloat16(v[f] - __bfloat162float(h));
    }
}

// ======================= main fused kernel =======================
extern __shared__ char smem_dyn[];

__global__ void __launch_bounds__(THREADS, 1)
rbf_main() {
    char* sm = smem_dyn;
    const uint32_t sb = smem_u32(sm);
    const int tid = threadIdx.x;
    const int l = tid & 31, w = tid >> 5;
    const int wm = w >> 1;          // 0..7 -> m32
    const int wn = w & 1;           // 0..1 -> n64
    const int m0 = blockIdx.x * TILE_M;
    const int split = blockIdx.y;

    // ---- prologue: async-stage z tiles + z norms + chunk 0 ----
    #pragma unroll
    for (int i = 0; i < 4; i++) {
        int idx = tid + THREADS * i;
        int row = idx >> 3, c = idx & 7;
        cpa16(sb + SM_ZH + swz(row, c), g_zh + (size_t)(m0 + row) * 64 + c * 8);
        cpa16(sb + SM_ZL + swz(row, c), g_zl + (size_t)(m0 + row) * 64 + c * 8);
    }
    if (tid < 256) cpa4(sb + SM_ZSN + tid * 4, g_zs + m0 + tid);
    {
        int n0 = split * CHUNK;
        #pragma unroll
        for (int i = 0; i < 2; i++) {
            int idx = tid + THREADS * i;
            int row = idx >> 3, c = idx & 7;
            cpa16(sb + SM_XH + swz(row, c), g_xh + (size_t)(n0 + row) * 64 + c * 8);
            cpa16(sb + SM_XL + swz(row, c), g_xl + (size_t)(n0 + row) * 64 + c * 8);
        }
        if (tid < 256) {
            int f = tid >> 4, c = tid & 15;
            cpa16(sb + SM_ATH + f * 272 + c * 16, g_ath + (size_t)f * N_PAD + n0 + c * 8);
            cpa16(sb + SM_ATL + f * 272 + c * 16, g_atl + (size_t)f * N_PAD + n0 + c * 8);
        }
        if (tid < 128) cpa4(sb + SM_XSN + tid * 4, g_xs + n0 + tid);
    }
    CP_COMMIT();
    CP_WAIT0();
    __syncthreads();

    const int g = l >> 2;
    float zsv[2][2];
    #pragma unroll
    for (int mi = 0; mi < 2; mi++) {
        zsv[mi][0] = *(const float*)(sm + SM_ZSN + (wm * 32 + mi * 16 + g) * 4);
        zsv[mi][1] = *(const float*)(sm + SM_ZSN + (wm * 32 + mi * 16 + g + 8) * 4);
    }

    // ldmatrix lane geometry
    const int la_row = wm * 32 + (l & 15);
    const int la_k   = l >> 4;
    const int lb_rw  = ((l >> 4) << 3) + (l & 7);   // 0..15 row-within-16
    const int lb_k   = (l >> 3) & 1;
    const int r7     = l & 7;
    const uint32_t baseZH = sb + SM_ZH + la_row * 128;
    const uint32_t baseZL = sb + SM_ZL + la_row * 128;
    const int lf_row = ((l >> 4) << 3) + (l & 7);   // alphaT f row 0..15

    float o[2][2][4] = {};
    const int T = (NCHUNK - 1 - split) / NSPLIT + 1;
    int buf = 0;

    for (int t = 0; t < T; t++) {
        const bool more = (t + 1 < T);
        // ---- issue async staging for chunk t+1 (overlaps compute) ----
        if (more) {
            int n0 = (split + (t + 1) * NSPLIT) * CHUNK;
            int nb = buf ^ 1;
            #pragma unroll
            for (int i = 0; i < 2; i++) {
                int idx = tid + THREADS * i;
                int row = idx >> 3, c = idx & 7;
                cpa16(sb + SM_XH + nb * 16384 + swz(row, c), g_xh + (size_t)(n0 + row) * 64 + c * 8);
                cpa16(sb + SM_XL + nb * 16384 + swz(row, c), g_xl + (size_t)(n0 + row) * 64 + c * 8);
            }
            if (tid < 256) {
                int f = tid >> 4, c = tid & 15;
                cpa16(sb + SM_ATH + nb * 4352 + f * 272 + c * 16,
                      g_ath + (size_t)f * N_PAD + n0 + c * 8);
                cpa16(sb + SM_ATL + nb * 4352 + f * 272 + c * 16,
                      g_atl + (size_t)f * N_PAD + n0 + c * 8);
            }
            if (tid < 128) cpa4(sb + SM_XSN + nb * 512 + tid * 4, g_xs + n0 + tid);
        }
        CP_COMMIT();

        const uint32_t bXH = sb + SM_XH + buf * 16384;
        const uint32_t bXL = sb + SM_XL + buf * 16384;

        // ---- two n32 halves: GEMM1 (bf16 3-pass) -> exp -> GEMM2 (bf16 3-pass) ----
        #pragma unroll
        for (int nh = 0; nh < 2; nh++) {
            const uint32_t baseB = (uint32_t)((wn * 64 + nh * 32 + lb_rw) * 128);
            float cacc[2][4][4] = {};
            #pragma unroll
            for (int ks = 0; ks < 4; ks++) {
                uint32_t offA = (uint32_t)(((ks * 2 + la_k) ^ r7) << 4);
                uint32_t offB = (uint32_t)(((ks * 2 + lb_k) ^ r7) << 4);
                uint32_t ah0[4], ah1[4], al0[4], al1[4];
                ldsm4(ah0, baseZH + offA);
                ldsm4(ah1, baseZH + 2048 + offA);
                ldsm4(al0, baseZL + offA);
                ldsm4(al1, baseZL + 2048 + offA);
                #pragma unroll
                for (int ng = 0; ng < 2; ng++) {
                    uint32_t bh[4], bl[4];
                    ldsm4(bh, bXH + baseB + ng * 2048 + offB);
                    ldsm4(bl, bXL + baseB + ng * 2048 + offB);
                    mma_bf16(cacc[0][2*ng],   ah0, bh[0], bh[1]);
                    mma_bf16(cacc[0][2*ng+1], ah0, bh[2], bh[3]);
                    mma_bf16(cacc[1][2*ng],   ah1, bh[0], bh[1]);
                    mma_bf16(cacc[1][2*ng+1], ah1, bh[2], bh[3]);
                    mma_bf16(cacc[0][2*ng],   al0, bh[0], bh[1]);
                    mma_bf16(cacc[0][2*ng+1], al0, bh[2], bh[3]);
                    mma_bf16(cacc[1][2*ng],   al1, bh[0], bh[1]);
                    mma_bf16(cacc[1][2*ng+1], al1, bh[2], bh[3]);
                    mma_bf16(cacc[0][2*ng],   ah0, bl[0], bl[1]);
                    mma_bf16(cacc[0][2*ng+1], ah0, bl[2], bl[3]);
                    mma_bf16(cacc[1][2*ng],   ah1, bl[0], bl[1]);
                    mma_bf16(cacc[1][2*ng+1], ah1, bl[2], bl[3]);
                }
            }

            // epilogue: w = exp2(c*log2e - zs' - xs'), split bf16 hi/lo, GEMM2 3-pass
            const uint32_t aTbh = sb + SM_ATH + buf * 4352 + lf_row * 272
                                + (uint32_t)((wn * 64 + nh * 32 + lb_k * 8) * 2);
            const uint32_t aTbl = sb + SM_ATL + buf * 4352 + lf_row * 272
                                + (uint32_t)((wn * 64 + nh * 32 + lb_k * 8) * 2);
            #pragma unroll
            for (int kg = 0; kg < 2; kg++) {
                uint32_t fH[2][4], fL[2][4];
                #pragma unroll
                for (int mi = 0; mi < 2; mi++) {
                    #pragma unroll
                    for (int q = 0; q < 2; q++) {
                        int nt = 2 * kg + q;
                        float2 xsp = *(const float2*)(sm + SM_XSN + buf * 512 +
                                      (wn * 64 + nh * 32 + nt * 8 + (l & 3) * 2) * 4);
                        float* c = cacc[mi][nt];
                        float w0 = ex2f(fmaf(c[0], L2E, -(zsv[mi][0] + xsp.x)));
                        float w1 = ex2f(fmaf(c[1], L2E, -(zsv[mi][0] + xsp.y)));
                        float w2 = ex2f(fmaf(c[2], L2E, -(zsv[mi][1] + xsp.x)));
                        float w3 = ex2f(fmaf(c[3], L2E, -(zsv[mi][1] + xsp.y)));
                        uint32_t p01 = pack_bf16(w1, w0);
                        uint32_t p23 = pack_bf16(w3, w2);
                        float h0 = __uint_as_float((p01 & 0xffffu) << 16);
                        float h1 = __uint_as_float(p01 & 0xffff0000u);
                        float h2 = __uint_as_float((p23 & 0xffffu) << 16);
                        float h3 = __uint_as_float(p23 & 0xffff0000u);
                        fH[mi][2*q]   = p01;
                        fH[mi][2*q+1] = p23;
                        fL[mi][2*q]   = pack_bf16(w1 - h1, w0 - h0);
                        fL[mi][2*q+1] = pack_bf16(w3 - h3, w2 - h2);
                    }
                }
                uint32_t ath[4], atl[4];
                ldsm4(ath, aTbh + kg * 32);
                ldsm4(atl, aTbl + kg * 32);
                #pragma unroll
                for (int mi = 0; mi < 2; mi++) {
                    mma_bf16(o[mi][0], fH[mi], ath[0], ath[1]);
                    mma_bf16(o[mi][1], fH[mi], ath[2], ath[3]);
                    mma_bf16(o[mi][0], fL[mi], ath[0], ath[1]);
                    mma_bf16(o[mi][1], fL[mi], ath[2], ath[3]);
                    mma_bf16(o[mi][0], fH[mi], atl[0], atl[1]);
                    mma_bf16(o[mi][1], fH[mi], atl[2], atl[3]);
                }
            }
        }

        CP_WAIT0();
        __syncthreads();
        if (more) buf ^= 1;
    }

    // ---- reduce across the 2 wn warps, write partials ----
    float* red = (float*)sm;                 // [256][16] f32, reuses z-tile space
    if (wn == 1) {
        #pragma unroll
        for (int mi = 0; mi < 2; mi++)
            #pragma unroll
            for (int ft = 0; ft < 2; ft++) {
                int mr = wm * 32 + mi * 16 + g;
                int f0 = ft * 8 + (l & 3) * 2;
                *(float2*)(red + mr * 16 + f0)       = make_float2(o[mi][ft][0], o[mi][ft][1]);
                *(float2*)(red + (mr + 8) * 16 + f0) = make_float2(o[mi][ft][2], o[mi][ft][3]);
            }
    }
    __syncthreads();
    if (wn == 0) {
        float* dst = g_part + ((size_t)split * B_TOTAL + m0) * F_DIM;
        #pragma unroll
        for (int mi = 0; mi < 2; mi++)
            #pragma unroll
            for (int ft = 0; ft < 2; ft++) {
                int mr = wm * 32 + mi * 16 + g;
                int f0 = ft * 8 + (l & 3) * 2;
                float2 a = *(float2*)(red + mr * 16 + f0);
                float2 b = *(float2*)(red + (mr + 8) * 16 + f0);
                *(float2*)(dst + mr * 16 + f0) =
                    make_float2(o[mi][ft][0] + a.x, o[mi][ft][1] + a.y);
                *(float2*)(dst + (mr + 8) * 16 + f0) =
                    make_float2(o[mi][ft][2] + b.x, o[mi][ft][3] + b.y);
            }
    }
}

// Deterministic reduction of the NSPLIT partial buffers.
__global__ void rbf_reduce(float* __restrict__ out) {
    int gid = blockIdx.x * blockDim.x + threadIdx.x;
    if (gid >= B_TOTAL * F_DIM) return;
    float s = 0.f;
    #pragma unroll
    for (int c = 0; c < NSPLIT; c++) s += g_part[(size_t)c * (B_TOTAL * F_DIM) + gid];
    out[gid] = s;
}

extern "C" void kernel_launch(void* const* d_in, const int* in_sizes, int n_in,
                              void* d_out, int out_size) {
    const float* z       = (const float*)d_in[0];   // [2048, 64]
    const float* dataset = (const float*)d_in[1];   // [100000, 64]
    const float* alpha   = (const float*)d_in[2];   // [100000, 16]
    float* out = (float*)d_out;                     // [2048, 16]
    (void)in_sizes; (void)n_in; (void)out_size;

    const int rows = N_PAD + B_TOTAL;
    prep_rows<<<(rows * 32 + 255) / 256, 256>>>(z, dataset);
    prep_at<<<(N_PAD + 255) / 256, 256>>>(alpha);

    cudaFuncSetAttribute(rbf_main, cudaFuncAttributeMaxDynamicSharedMemorySize, SMEM_BYTES);
    dim3 grid(B_TOTAL / TILE_M, NSPLIT);
    rbf_main<<<grid, THREADS, SMEM_BYTES>>>();
    rbf_reduce<<<(B_TOTAL * F_DIM + 255) / 256, 256>>>(out);
}